// round 8
// baseline (speedup 1.0000x reference)
#include <cuda_runtime.h>
#include <cstdint>

// Problem shape (fixed by the reference)
#define BATCH 64
#define SEQ   8
#define VOCAB 128000

// Pass 1: 2 splits per row -> 128 blocks (one wave over ~128 SMs).
// Each split: 64000 floats = 16000 float4; 512 threads -> 31-32 f4/thread.
#define SPLITS       2
#define THREADS      512
#define SPLIT_FLOATS (VOCAB / SPLITS)       // 64000
#define SPLIT_F4     (SPLIT_FLOATS / 4)     // 16000

// Scratch for per-split partials (no cudaMalloc allowed)
__device__ float g_pmax[BATCH * SPLITS];
__device__ int   g_pidx[BATCH * SPLITS];

__device__ __forceinline__ void take_better(float v, int i, float& bm, int& bi) {
    // jnp.argmax: first occurrence wins -> on tie keep smaller index
    if (v > bm || (v == bm && i < bi)) { bm = v; bi = i; }
}

__global__ __launch_bounds__(THREADS) void argmax_pass1(const float* __restrict__ logits)
{
    const int row   = blockIdx.x >> 1;      // 0..63
    const int split = blockIdx.x & 1;       // 0..1

    const float4* __restrict__ p = reinterpret_cast<const float4*>(
        logits + (size_t)row * (SEQ * VOCAB) + (size_t)(SEQ - 1) * VOCAB
               + (size_t)split * SPLIT_FLOATS);

    const int tid = threadIdx.x;
    const int idx_base = split * SPLIT_FLOATS;

    float bm = -__int_as_float(0x7f800000);  // -inf
    int   bi = 0x7fffffff;

    for (int f4 = tid; f4 < SPLIT_F4; f4 += THREADS) {
        float4 v = p[f4];
        const int e = idx_base + f4 * 4;
        take_better(v.x, e + 0, bm, bi);
        take_better(v.y, e + 1, bm, bi);
        take_better(v.z, e + 2, bm, bi);
        take_better(v.w, e + 3, bm, bi);
    }

    // intra-warp reduce
    #pragma unroll
    for (int off = 16; off > 0; off >>= 1) {
        float om = __shfl_down_sync(0xffffffffu, bm, off);
        int   oi = __shfl_down_sync(0xffffffffu, bi, off);
        take_better(om, oi, bm, bi);
    }

    __shared__ float sm[THREADS / 32];  // 16 warps
    __shared__ int   si[THREADS / 32];
    const int lane = tid & 31, warp = tid >> 5;
    if (lane == 0) { sm[warp] = bm; si[warp] = bi; }
    __syncthreads();

    if (warp == 0) {
        bm = (lane < THREADS / 32) ? sm[lane] : -__int_as_float(0x7f800000);
        bi = (lane < THREADS / 32) ? si[lane] : 0x7fffffff;
        #pragma unroll
        for (int off = 8; off > 0; off >>= 1) {
            float om = __shfl_down_sync(0xffffffffu, bm, off);
            int   oi = __shfl_down_sync(0xffffffffu, bi, off);
            take_better(om, oi, bm, bi);
        }
        if (lane == 0) {
            g_pmax[row * SPLITS + split] = bm;
            g_pidx[row * SPLITS + split] = bi;
        }
    }
}

__global__ void argmax_pass2(float* __restrict__ out)
{
    const int row = threadIdx.x;  // 0..63
    if (row >= BATCH) return;
    float bm = g_pmax[row * SPLITS + 0];
    int   bi = g_pidx[row * SPLITS + 0];
    #pragma unroll
    for (int s = 1; s < SPLITS; ++s) {
        float v = g_pmax[row * SPLITS + s];
        int   i = g_pidx[row * SPLITS + s];
        // ascending split order + strict > keeps first occurrence on ties
        if (v > bm) { bm = v; bi = i; }
        else if (v == bm && i < bi) { bi = i; }
    }
    // KEY FIX: harness compares outputs as float32 (normalized rel-err).
    // Indices < 2^24 are exactly representable.
    out[row] = (float)bi;
}

extern "C" void kernel_launch(void* const* d_in, const int* in_sizes, int n_in,
                              void* d_out, int out_size) {
    const float* logits = (const float*)d_in[0];
    argmax_pass1<<<BATCH * SPLITS, THREADS>>>(logits);
    argmax_pass2<<<1, BATCH>>>((float*)d_out);
}

// round 9
// speedup vs baseline: 1.0233x; 1.0233x over previous
#include <cuda_runtime.h>
#include <cstdint>

// Problem shape (fixed by the reference)
#define BATCH 64
#define SEQ   8
#define VOCAB 128000

// 2 splits per row -> 128 blocks (single wave over 148 SMs).
// Each split: 64000 floats = 16000 float4; 512 threads.
#define SPLITS       2
#define THREADS      512
#define SPLIT_FLOATS (VOCAB / SPLITS)       // 64000
#define SPLIT_F4     (SPLIT_FLOATS / 4)     // 16000

// Scratch (no cudaMalloc allowed). g_count zero-initialized and reset by the
// last-arriving block each run -> deterministic across graph replays.
__device__ float g_pmax[BATCH * SPLITS];
__device__ int   g_pidx[BATCH * SPLITS];
__device__ int   g_count[BATCH];

__device__ __forceinline__ void take_better(float v, int i, float& bm, int& bi) {
    // jnp.argmax: first occurrence wins -> on tie keep smaller index
    if (v > bm || (v == bm && i < bi)) { bm = v; bi = i; }
}

__global__ __launch_bounds__(THREADS) void argmax_fused(
    const float* __restrict__ logits, float* __restrict__ out)
{
    const int row   = blockIdx.x >> 1;      // 0..63
    const int split = blockIdx.x & 1;       // 0..1

    const float4* __restrict__ p = reinterpret_cast<const float4*>(
        logits + (size_t)row * (SEQ * VOCAB) + (size_t)(SEQ - 1) * VOCAB
               + (size_t)split * SPLIT_FLOATS);

    const int tid = threadIdx.x;
    const int idx_base = split * SPLIT_FLOATS;

    float bm = -__int_as_float(0x7f800000);  // -inf
    int   bi = 0x7fffffff;

    // 16000 f4 / 512 threads = 31.25 iters; unroll to front-batch LDG.128s
    #pragma unroll 8
    for (int f4 = tid; f4 < SPLIT_F4; f4 += THREADS) {
        float4 v = p[f4];
        const int e = idx_base + f4 * 4;
        take_better(v.x, e + 0, bm, bi);
        take_better(v.y, e + 1, bm, bi);
        take_better(v.z, e + 2, bm, bi);
        take_better(v.w, e + 3, bm, bi);
    }

    // intra-warp reduce
    #pragma unroll
    for (int off = 16; off > 0; off >>= 1) {
        float om = __shfl_down_sync(0xffffffffu, bm, off);
        int   oi = __shfl_down_sync(0xffffffffu, bi, off);
        take_better(om, oi, bm, bi);
    }

    __shared__ float sm[THREADS / 32];  // 16 warps
    __shared__ int   si[THREADS / 32];
    const int lane = tid & 31, warp = tid >> 5;
    if (lane == 0) { sm[warp] = bm; si[warp] = bi; }
    __syncthreads();

    if (warp == 0) {
        bm = (lane < THREADS / 32) ? sm[lane] : -__int_as_float(0x7f800000);
        bi = (lane < THREADS / 32) ? si[lane] : 0x7fffffff;
        #pragma unroll
        for (int off = 8; off > 0; off >>= 1) {
            float om = __shfl_down_sync(0xffffffffu, bm, off);
            int   oi = __shfl_down_sync(0xffffffffu, bi, off);
            take_better(om, oi, bm, bi);
        }
        if (lane == 0) {
            // publish this split's partial
            g_pmax[row * SPLITS + split] = bm;
            g_pidx[row * SPLITS + split] = bi;
            __threadfence();
            int old = atomicAdd(&g_count[row], 1);
            if (old == SPLITS - 1) {
                // last arriver merges (fence above makes peer's writes visible)
                float m0 = g_pmax[row * SPLITS + 0];
                float m1 = g_pmax[row * SPLITS + 1];
                int   i0 = g_pidx[row * SPLITS + 0];
                int   i1 = g_pidx[row * SPLITS + 1];
                // split 0 has smaller indices: strict > keeps first occurrence
                float fm = m0; int fi = i0;
                if (m1 > fm) { fm = m1; fi = i1; }
                out[row] = (float)fi;   // harness compares as float32
                g_count[row] = 0;       // reset for next graph replay
            }
        }
    }
}

extern "C" void kernel_launch(void* const* d_in, const int* in_sizes, int n_in,
                              void* d_out, int out_size) {
    const float* logits = (const float*)d_in[0];
    argmax_fused<<<BATCH * SPLITS, THREADS>>>(logits, (float*)d_out);
}

// round 10
// speedup vs baseline: 1.0476x; 1.0238x over previous
#include <cuda_runtime.h>
#include <cstdint>

// Problem shape (fixed by the reference)
#define BATCH 64
#define SEQ   8
#define VOCAB 128000

// 2 splits per row -> 128 blocks (single wave over 148 SMs).
#define SPLITS       2
#define THREADS      512
#define SPLIT_FLOATS (VOCAB / SPLITS)       // 64000
#define SPLIT_F4     (SPLIT_FLOATS / 4)     // 16000
#define FULL_ITERS   (SPLIT_F4 / THREADS)   // 31
#define REM          (SPLIT_F4 % THREADS)   // 128

// Scratch (no cudaMalloc allowed). g_count starts 0 and is reset by the
// last-arriving block each run -> deterministic across graph replays.
__device__ float g_pmax[BATCH * SPLITS];
__device__ int   g_pidx[BATCH * SPLITS];
__device__ int   g_count[BATCH];

__device__ __forceinline__ void take_better(float v, int i, float& bm, int& bi) {
    // full tie-break (first occurrence = smaller index) for cross-thread merge
    if (v > bm || (v == bm && i < bi)) { bm = v; bi = i; }
}

// In-thread scan: indices strictly increase, so strict > keeps first occurrence.
// fmaxf tree gives ILP; index recovery only on the rare update path.
__device__ __forceinline__ void proc(float4 v, int e, float& bm, int& bi) {
    float m01 = fmaxf(v.x, v.y);
    float m23 = fmaxf(v.z, v.w);
    float m   = fmaxf(m01, m23);
    if (m > bm) {
        bm = m;
        bi = (m == v.x) ? e : (m == v.y) ? e + 1 : (m == v.z) ? e + 2 : e + 3;
    }
}

__global__ __launch_bounds__(THREADS, 1) void argmax_fused(
    const float* __restrict__ logits, float* __restrict__ out)
{
    const int row   = blockIdx.x >> 1;      // 0..63
    const int split = blockIdx.x & 1;       // 0..1

    const float4* __restrict__ p = reinterpret_cast<const float4*>(
        logits + (size_t)row * (SEQ * VOCAB) + (size_t)(SEQ - 1) * VOCAB
               + (size_t)split * SPLIT_FLOATS);

    const int tid = threadIdx.x;
    const int idx_base = split * SPLIT_FLOATS;

    float bm = -__int_as_float(0x7f800000);  // -inf
    int   bi = 0x7fffffff;

    // Explicitly batched loads: 8 LDG.128 in flight per thread per batch.
    float4 buf[8];
    #pragma unroll
    for (int j0 = 0; j0 < 24; j0 += 8) {
        #pragma unroll
        for (int u = 0; u < 8; ++u) buf[u] = p[tid + (j0 + u) * THREADS];
        #pragma unroll
        for (int u = 0; u < 8; ++u)
            proc(buf[u], idx_base + (tid + (j0 + u) * THREADS) * 4, bm, bi);
    }
    // tail: 7 full iterations (j = 24..30)
    #pragma unroll
    for (int u = 0; u < 7; ++u) buf[u] = p[tid + (24 + u) * THREADS];
    #pragma unroll
    for (int u = 0; u < 7; ++u)
        proc(buf[u], idx_base + (tid + (24 + u) * THREADS) * 4, bm, bi);
    // remainder: only first REM threads have a 32nd element
    if (tid < REM) {
        float4 v = p[tid + FULL_ITERS * THREADS];
        proc(v, idx_base + (tid + FULL_ITERS * THREADS) * 4, bm, bi);
    }

    // intra-warp reduce (full tie-break)
    #pragma unroll
    for (int off = 16; off > 0; off >>= 1) {
        float om = __shfl_down_sync(0xffffffffu, bm, off);
        int   oi = __shfl_down_sync(0xffffffffu, bi, off);
        take_better(om, oi, bm, bi);
    }

    __shared__ float sm[THREADS / 32];  // 16 warps
    __shared__ int   si[THREADS / 32];
    const int lane = tid & 31, warp = tid >> 5;
    if (lane == 0) { sm[warp] = bm; si[warp] = bi; }
    __syncthreads();

    if (warp == 0) {
        bm = (lane < THREADS / 32) ? sm[lane] : -__int_as_float(0x7f800000);
        bi = (lane < THREADS / 32) ? si[lane] : 0x7fffffff;
        #pragma unroll
        for (int off = 8; off > 0; off >>= 1) {
            float om = __shfl_down_sync(0xffffffffu, bm, off);
            int   oi = __shfl_down_sync(0xffffffffu, bi, off);
            take_better(om, oi, bm, bi);
        }
        if (lane == 0) {
            g_pmax[row * SPLITS + split] = bm;
            g_pidx[row * SPLITS + split] = bi;
            __threadfence();
            int old = atomicAdd(&g_count[row], 1);
            if (old == SPLITS - 1) {
                float m0 = g_pmax[row * SPLITS + 0];
                float m1 = g_pmax[row * SPLITS + 1];
                int   i0 = g_pidx[row * SPLITS + 0];
                int   i1 = g_pidx[row * SPLITS + 1];
                // split 0 has smaller indices: strict > keeps first occurrence
                float fm = m0; int fi = i0;
                if (m1 > fm) { fm = m1; fi = i1; }
                out[row] = (float)fi;   // harness compares as float32
                g_count[row] = 0;       // reset for next graph replay
            }
        }
    }
}

extern "C" void kernel_launch(void* const* d_in, const int* in_sizes, int n_in,
                              void* d_out, int out_size) {
    const float* logits = (const float*)d_in[0];
    argmax_fused<<<BATCH * SPLITS, THREADS>>>(logits, (float*)d_out);
}